// round 10
// baseline (speedup 1.0000x reference)
#include <cuda_runtime.h>
#include <cuda_bf16.h>
#include <cstdint>

#define B_TOT 65536
#define N_EMB 1024
#define KMED  32768
#define TEMP_F 0.07f

#define OUT_LOSS 4194304
#define OUT_IDX  4194305
#define OUT_NW   4259841
#define OUT_EP   4325377

#define WLO  (-0.01f)
#define WHI  (0.01f)
#define TOPT (0.33f)
#define EXLO (-0.28f)
#define WCAP 8192
#define TCAP 1024
#define WBCAP 32
#define TBCAP 8
#define HB   256
#define GCAP 256

#define TSTRIDE 48          // bytes per tile row (16 bf16 data + 8 pad)
#define TBYTES  (128 * TSTRIDE)

// bf16 triple-split operands (row-major, 64 bf16 = 128B rows)
__device__ __nv_bfloat162 g_a1[(size_t)B_TOT * 32];
__device__ __nv_bfloat162 g_a2[(size_t)B_TOT * 32];
__device__ __nv_bfloat162 g_a3[(size_t)B_TOT * 32];
__device__ __nv_bfloat162 g_b1[N_EMB * 32];
__device__ __nv_bfloat162 g_b2[N_EMB * 32];
__device__ __nv_bfloat162 g_b3[N_EMB * 32];
__device__ unsigned long long g_rowmax[B_TOT];
__device__ unsigned long long g_colmax[N_EMB];
__device__ int g_counts[N_EMB];
__device__ double g_mse;
__device__ double g_contra;
__device__ float    g_W[(size_t)N_EMB * WCAP];
__device__ float    g_T[(size_t)N_EMB * TCAP];
__device__ unsigned g_wc[N_EMB];
__device__ unsigned g_tc[N_EMB];
__device__ int      g_cnt_lo[N_EMB];
__device__ float    g_se_lo[N_EMB];

__device__ __forceinline__ unsigned keyf(float f) {
    unsigned u = __float_as_uint(f);
    return (u & 0x80000000u) ? ~u : (u | 0x80000000u);
}
__device__ __forceinline__ unsigned long long packvi(float v, unsigned idx) {
    return ((unsigned long long)keyf(v) << 32) | (unsigned long long)(0xFFFFFFFFu - idx);
}
__device__ __forceinline__ uint32_t smem_u32(const void* p) {
    uint32_t a;
    asm("{ .reg .u64 t; cvta.to.shared.u64 t, %1; cvt.u32.u64 %0, t; }" : "=r"(a) : "l"(p));
    return a;
}

__global__ void k_init() {
    int i = blockIdx.x * blockDim.x + threadIdx.x;
    if (i < B_TOT) g_rowmax[i] = 0ull;
    if (i < N_EMB) {
        g_colmax[i] = 0ull; g_counts[i] = 0;
        g_wc[i] = 0u; g_tc[i] = 0u; g_cnt_lo[i] = 0; g_se_lo[i] = 0.f;
    }
    if (i == 0) { g_mse = 0.0; g_contra = 0.0; }
}

__device__ __forceinline__ void norm_split(const float* __restrict__ in,
                                           __nv_bfloat162* o1, __nv_bfloat162* o2,
                                           __nv_bfloat162* o3, int row, int lane) {
    float2 v = ((const float2*)(in + (size_t)row * 64))[lane];
    float s = v.x * v.x + v.y * v.y;
    #pragma unroll
    for (int o = 16; o; o >>= 1) s += __shfl_xor_sync(0xFFFFFFFFu, s, o);
    float dn = fmaxf(sqrtf(s), 1e-12f);
    float nx = v.x / dn, ny = v.y / dn;
    __nv_bfloat16 x1 = __float2bfloat16(nx), y1 = __float2bfloat16(ny);
    float rx = nx - __bfloat162float(x1), ry = ny - __bfloat162float(y1);
    __nv_bfloat16 x2 = __float2bfloat16(rx), y2 = __float2bfloat16(ry);
    rx -= __bfloat162float(x2); ry -= __bfloat162float(y2);
    __nv_bfloat16 x3 = __float2bfloat16(rx), y3 = __float2bfloat16(ry);
    size_t idx = (size_t)row * 32 + lane;
    o1[idx] = __nv_bfloat162(x1, y1);
    o2[idx] = __nv_bfloat162(x2, y2);
    o3[idx] = __nv_bfloat162(x3, y3);
}
__global__ void k_norm_z(const float* __restrict__ z) {
    int w = (blockIdx.x * blockDim.x + threadIdx.x) >> 5;
    if (w < B_TOT) norm_split(z, g_a1, g_a2, g_a3, w, threadIdx.x & 31);
}
__global__ void k_norm_c(const float* __restrict__ ew) {
    int w = (blockIdx.x * blockDim.x + threadIdx.x) >> 5;
    if (w < N_EMB) norm_split(ew, g_b1, g_b2, g_b3, w, threadIdx.x & 31);
}

// tensor-core GEMM via mma.sync bf16, 6-term split, fused epilogue.
__global__ __launch_bounds__(256) void k_gemm_tc() {
    __shared__ __align__(16) char smem[6 * TBYTES];   // 36864B
    int tid = threadIdx.x, wid = tid >> 5, lane = tid & 31;
    int warp_m = wid >> 2, warp_n = wid & 3;          // 2 x 4 warp grid
    int n0 = blockIdx.x * 128, m0 = blockIdx.y * 128;
    uint32_t sb = smem_u32(smem);

    float acc[4][4][4];
    #pragma unroll
    for (int a = 0; a < 4; a++)
        #pragma unroll
        for (int b = 0; b < 4; b++)
            #pragma unroll
            for (int c = 0; c < 4; c++) acc[a][b][c] = 0.f;

    const char* srcs[6] = {
        (const char*)(g_a1 + (size_t)m0 * 32), (const char*)(g_a2 + (size_t)m0 * 32),
        (const char*)(g_a3 + (size_t)m0 * 32), (const char*)(g_b1 + (size_t)n0 * 32),
        (const char*)(g_b2 + (size_t)n0 * 32), (const char*)(g_b3 + (size_t)n0 * 32)};
    const int TA[6] = {0, 0, 1, 0, 2, 1};
    const int TB[6] = {0, 1, 0, 2, 0, 1};

    // ldmatrix source addresses (per-thread invariant parts)
    uint32_t aRow = (uint32_t)(warp_m * 64 + (lane & 7) + ((lane >> 3) & 1) * 8);
    uint32_t aKof = (uint32_t)((lane >> 4) * 16);          // (lane>>4)*8 cols * 2B
    int lb = lane & 15;
    uint32_t bRow = (uint32_t)(warp_n * 32 + (lb & 7));
    uint32_t bKof = (uint32_t)((lb >> 3) * 16);

    for (int kt = 0; kt < 4; kt++) {
        __syncthreads();
        // load 6 tiles: 128 rows x 32B each from global kcol = kt*16
        #pragma unroll
        for (int t = 0; t < 6; t++) {
            int r = tid >> 1, u = tid & 1;
            *(uint4*)(smem + t * TBYTES + r * TSTRIDE + u * 16) =
                *(const uint4*)(srcs[t] + r * 128 + kt * 32 + u * 16);
        }
        __syncthreads();
        #pragma unroll
        for (int t = 0; t < 6; t++) {
            uint32_t tAb = sb + TA[t] * TBYTES;
            uint32_t tBb = sb + (3 + TB[t]) * TBYTES;
            uint32_t bf[4][2];
            #pragma unroll
            for (int nt = 0; nt < 4; nt++) {
                uint32_t addr = tBb + (bRow + nt * 8) * TSTRIDE + bKof;
                asm volatile("ldmatrix.sync.aligned.m8n8.x2.shared.b16 {%0,%1}, [%2];"
                             : "=r"(bf[nt][0]), "=r"(bf[nt][1]) : "r"(addr));
            }
            #pragma unroll
            for (int mt = 0; mt < 4; mt++) {
                uint32_t a0, a1, a2, a3;
                uint32_t addr = tAb + (aRow + mt * 16) * TSTRIDE + aKof;
                asm volatile("ldmatrix.sync.aligned.m8n8.x4.shared.b16 {%0,%1,%2,%3}, [%4];"
                             : "=r"(a0), "=r"(a1), "=r"(a2), "=r"(a3) : "r"(addr));
                #pragma unroll
                for (int nt = 0; nt < 4; nt++) {
                    asm volatile(
                        "mma.sync.aligned.m16n8k16.row.col.f32.bf16.bf16.f32 "
                        "{%0,%1,%2,%3},{%4,%5,%6,%7},{%8,%9},{%0,%1,%2,%3};"
                        : "+f"(acc[mt][nt][0]), "+f"(acc[mt][nt][1]),
                          "+f"(acc[mt][nt][2]), "+f"(acc[mt][nt][3])
                        : "r"(a0), "r"(a1), "r"(a2), "r"(a3),
                          "r"(bf[nt][0]), "r"(bf[nt][1]));
                }
            }
        }
    }

    // ---------------- epilogue (aliases smem) ----------------
    __syncthreads();
    unsigned long long* srow_s = (unsigned long long*)smem;          // [128] 1024B
    unsigned long long* scol_s = (unsigned long long*)(smem + 1024); // [128] 1024B
    int*      s_cnt = (int*)(smem + 2048);
    float*    s_se  = (float*)(smem + 2560);
    unsigned* s_wn  = (unsigned*)(smem + 3072);
    unsigned* s_tn  = (unsigned*)(smem + 3584);
    float*    s_wbuf = (float*)(smem + 4096);                        // [128][WBCAP]
    float*    s_tbuf = (float*)(smem + 20480);                       // [128][TBCAP]
    if (tid < 128) {
        srow_s[tid] = 0ull; scol_s[tid] = 0ull;
        s_cnt[tid] = 0; s_se[tid] = 0.f; s_wn[tid] = 0u; s_tn[tid] = 0u;
    }
    __syncthreads();

    int r0 = lane >> 2, c0 = (lane & 3) * 2;
    // row argmax: thread-local over 8 cols (ascending), then 4-lane butterfly
    #pragma unroll
    for (int mt = 0; mt < 4; mt++)
        #pragma unroll
        for (int h = 0; h < 2; h++) {
            int rl = warp_m * 64 + mt * 16 + h * 8 + r0;
            float bv = -2.f; int bc = 0;
            #pragma unroll
            for (int nt = 0; nt < 4; nt++)
                #pragma unroll
                for (int q = 0; q < 2; q++) {
                    float v = acc[mt][nt][h * 2 + q];
                    int c = warp_n * 32 + nt * 8 + c0 + q;
                    if (v > bv) { bv = v; bc = c; }
                }
            unsigned long long m = packvi(bv, (unsigned)(n0 + bc));
            #pragma unroll
            for (int o = 1; o < 4; o <<= 1) {
                unsigned long long v = __shfl_xor_sync(0xFFFFFFFFu, m, o);
                if (v > m) m = v;
            }
            if ((lane & 3) == 0) atomicMax(&srow_s[rl], m);
        }
    // col argmax: thread-local over 8 rows (ascending), then 8-lane butterfly
    #pragma unroll
    for (int nt = 0; nt < 4; nt++)
        #pragma unroll
        for (int q = 0; q < 2; q++) {
            int cl = warp_n * 32 + nt * 8 + c0 + q;
            float bv = -2.f; int br = 0;
            #pragma unroll
            for (int mt = 0; mt < 4; mt++)
                #pragma unroll
                for (int h = 0; h < 2; h++) {
                    float v = acc[mt][nt][h * 2 + q];
                    if (v > bv) { bv = v; br = warp_m * 64 + mt * 16 + h * 8 + r0; }
                }
            unsigned long long m = packvi(bv, (unsigned)(m0 + br));
            #pragma unroll
            for (int o = 4; o < 32; o <<= 1) {
                unsigned long long v = __shfl_xor_sync(0xFFFFFFFFu, m, o);
                if (v > m) m = v;
            }
            if ((lane >> 2) == 0) atomicMax(&scol_s[cl], m);
        }
    // selection stats + shared-buffered gather
    const float invT = 1.0f / TEMP_F;
    #pragma unroll
    for (int nt = 0; nt < 4; nt++)
        #pragma unroll
        for (int q = 0; q < 2; q++) {
            int cl = warp_n * 32 + nt * 8 + c0 + q;
            int n = n0 + cl;
            int cnt = 0; float se = 0.f;
            #pragma unroll
            for (int mt = 0; mt < 4; mt++)
                #pragma unroll
                for (int h = 0; h < 2; h++) {
                    float v = acc[mt][nt][h * 2 + q];
                    if (v < WLO) {
                        cnt++;
                        if (v >= EXLO) se += __expf(v * invT);
                    } else if (v < WHI) {
                        unsigned p = atomicAdd(&s_wn[cl], 1u);
                        if (p < WBCAP) s_wbuf[cl * WBCAP + p] = v;
                        else { unsigned g = atomicAdd(&g_wc[n], 1u); if (g < WCAP) g_W[(size_t)n * WCAP + g] = v; }
                    } else if (v >= TOPT) {
                        unsigned p = atomicAdd(&s_tn[cl], 1u);
                        if (p < TBCAP) s_tbuf[cl * TBCAP + p] = v;
                        else { unsigned g = atomicAdd(&g_tc[n], 1u); if (g < TCAP) g_T[(size_t)n * TCAP + g] = v; }
                    }
                }
            if (cnt) { atomicAdd(&s_cnt[cl], cnt); if (se != 0.f) atomicAdd(&s_se[cl], se); }
        }
    __syncthreads();
    if (tid < 128) {
        int n = n0 + tid;
        atomicMax(&g_rowmax[m0 + tid], srow_s[tid]);
        atomicMax(&g_colmax[n], scol_s[tid]);
        if (s_cnt[tid]) atomicAdd(&g_cnt_lo[n], s_cnt[tid]);
        if (s_se[tid] != 0.f) atomicAdd(&g_se_lo[n], s_se[tid]);
        unsigned wn = min(s_wn[tid], (unsigned)WBCAP);
        if (wn) {
            unsigned base = atomicAdd(&g_wc[n], wn);
            for (unsigned h = 0; h < wn; h++)
                if (base + h < WCAP) g_W[(size_t)n * WCAP + base + h] = s_wbuf[tid * WBCAP + h];
        }
        unsigned tn = min(s_tn[tid], (unsigned)TBCAP);
        if (tn) {
            unsigned base = atomicAdd(&g_tc[n], tn);
            for (unsigned h = 0; h < tn; h++)
                if (base + h < TCAP) g_T[(size_t)n * TCAP + base + h] = s_tbuf[tid * TBCAP + h];
        }
    }
}

__global__ __launch_bounds__(256) void k_rows(const float* __restrict__ z,
                                              const float* __restrict__ ew,
                                              float* __restrict__ out_zq,
                                              float* __restrict__ out_idx) {
    int tid = threadIdx.x;
    int b = blockIdx.x * 4 + (tid >> 6);
    int d = tid & 63;
    unsigned nIdx = 0xFFFFFFFFu - (unsigned)(g_rowmax[b] & 0xFFFFFFFFull);
    float w  = ew[(size_t)nIdx * 64 + d];
    float zv = z[(size_t)b * 64 + d];
    float dq = w - zv;
    out_zq[(size_t)b * 64 + d] = zv + dq;
    float sq = dq * dq;
    #pragma unroll
    for (int o = 16; o; o >>= 1) sq += __shfl_xor_sync(0xFFFFFFFFu, sq, o);
    __shared__ float red[8];
    if ((tid & 31) == 0) red[tid >> 5] = sq;
    __syncthreads();
    if (tid == 0) {
        float s = 0.f;
        #pragma unroll
        for (int i = 0; i < 8; i++) s += red[i];
        atomicAdd(&g_mse, (double)s);
    }
    if (d == 0) {
        atomicAdd(&g_counts[nIdx], 1);
        out_idx[b] = (float)nIdx;
    }
}

__global__ __launch_bounds__(64) void k_cols(const float* __restrict__ z,
                                             const float* __restrict__ ew,
                                             const float* __restrict__ eprob,
                                             float* __restrict__ out_nw,
                                             float* __restrict__ out_ep) {
    int n = blockIdx.x, d = threadIdx.x;
    __shared__ float s_dec;
    __shared__ unsigned s_anchor;
    if (d == 0) {
        float cnt = (float)g_counts[n];
        float ep = eprob[n] * 0.99f + (cnt / 65536.0f) * 0.01f;
        out_ep[n] = ep;
        s_dec = expf(-((ep * 1024.0f * 10.0f) / 0.01f) - 0.001f);
        s_anchor = 0xFFFFFFFFu - (unsigned)(g_colmax[n] & 0xFFFFFFFFull);
    }
    __syncthreads();
    float dec = s_dec;
    float w = ew[(size_t)n * 64 + d];
    out_nw[(size_t)n * 64 + d] = w * (1.0f - dec) + z[(size_t)s_anchor * 64 + d] * dec;
}

__global__ __launch_bounds__(512) void k_select() {
    __shared__ unsigned cW[HB]; __shared__ float eW[HB];
    __shared__ unsigned cT[HB]; __shared__ float vT[HB];
    __shared__ float GW[GCAP], GT[GCAP];
    __shared__ unsigned s_gw, s_gt;
    __shared__ int s_bW, s_cumW, s_bT, s_cumT, s_cTb;
    __shared__ float s_seBelow, s_svAbove, s_tmed, s_ttop;
    int tid = threadIdx.x;
    int n = blockIdx.x;
    int cw  = (int)min(g_wc[n], (unsigned)WCAP);
    int ctp = (int)min(g_tc[n], (unsigned)TCAP);
    int C_lo = g_cnt_lo[n];
    float se_lo = g_se_lo[n];
    const float* Wp = &g_W[(size_t)n * WCAP];
    const float* Tp = &g_T[(size_t)n * TCAP];
    for (int i = tid; i < HB; i += 512) { cW[i] = 0u; eW[i] = 0.f; cT[i] = 0u; vT[i] = 0.f; }
    if (tid == 0) { s_gw = 0u; s_gt = 0u; s_tmed = WLO; s_ttop = TOPT; }
    __syncthreads();
    const float invT = 1.0f / TEMP_F;
    const float sclW = (float)HB / (WHI - WLO);
    const float sclT = (float)HB / (1.0f - TOPT);
    for (int i = tid; i < cw; i += 512) {
        float v = Wp[i];
        int b = min(max((int)((v - WLO) * sclW), 0), HB - 1);
        atomicAdd(&cW[b], 1u); atomicAdd(&eW[b], __expf(v * invT));
    }
    for (int i = tid; i < ctp; i += 512) {
        float v = Tp[i];
        int b = min(max((int)((v - TOPT) * sclT), 0), HB - 1);
        atomicAdd(&cT[b], 1u); atomicAdd(&vT[b], v);
    }
    __syncthreads();
    if (tid == 0) {
        int r = KMED - C_lo; if (r < 1) r = 1;
        int cum = 0; float se = 0.f; int b = 0;
        for (;; b++) { if (cum + (int)cW[b] >= r || b == HB - 1) break; cum += (int)cW[b]; se += eW[b]; }
        s_bW = b; s_cumW = cum; s_seBelow = se;
    } else if (tid == 32) {
        int r = ctp - 63; if (r < 1) r = 1;
        int cum = 0; int b = 0;
        for (;; b++) { if (cum + (int)cT[b] >= r || b == HB - 1) break; cum += (int)cT[b]; }
        float tot = 0.f, below = 0.f;
        for (int q = 0; q < HB; q++) tot += vT[q];
        for (int q = 0; q < b; q++) below += vT[q];
        s_bT = b; s_cumT = cum; s_cTb = (int)cT[b]; s_svAbove = tot - below - vT[b];
    }
    __syncthreads();
    int bW = s_bW, bT = s_bT;
    for (int i = tid; i < cw; i += 512) {
        float v = Wp[i];
        int b = min(max((int)((v - WLO) * sclW), 0), HB - 1);
        if (b == bW) { unsigned p = atomicAdd(&s_gw, 1u); if (p < GCAP) GW[p] = v; }
    }
    for (int i = tid; i < ctp; i += 512) {
        float v = Tp[i];
        int b = min(max((int)((v - TOPT) * sclT), 0), HB - 1);
        if (b == bT) { unsigned p = atomicAdd(&s_gt, 1u); if (p < GCAP) GT[p] = v; }
    }
    __syncthreads();
    int mW = (int)min(s_gw, (unsigned)GCAP);
    int mT = (int)min(s_gt, (unsigned)GCAP);
    int rW = KMED - C_lo - s_cumW; if (rW < 1) rW = 1; if (rW > mW) rW = mW;
    int rT = (ctp - 63) - s_cumT;  if (rT < 1) rT = 1; if (rT > mT) rT = mT;
    if (tid < mW) {
        float x = GW[tid]; int less = 0, eqb = 0;
        for (int j = 0; j < mW; j++) { float y = GW[j]; less += (y < x); eqb += (j < tid) && (y == x); }
        if (less + eqb + 1 == rW) s_tmed = x;
    }
    if (tid >= 256 && tid - 256 < mT) {
        int i = tid - 256; float x = GT[i]; int less = 0, eqb = 0;
        for (int j = 0; j < mT; j++) { float y = GT[j]; less += (y < x); eqb += (j < i) && (y == x); }
        if (less + eqb + 1 == rT) s_ttop = x;
    }
    __syncthreads();
    if (tid == 0) {
        float tmed = s_tmed, ttop = s_ttop;
        int cnt_lt = 0; float se_lt = 0.f;
        for (int j = 0; j < mW; j++) if (GW[j] < tmed) { cnt_lt++; se_lt += __expf(GW[j] * invT); }
        float Sexp = se_lo + s_seBelow + se_lt
                   + (float)(KMED - C_lo - s_cumW - cnt_lt) * __expf(tmed * invT);
        int cnt_gt = 0; float sv_gt = 0.f;
        for (int j = 0; j < mT; j++) if (GT[j] > ttop) { cnt_gt++; sv_gt += GT[j]; }
        int aboveBins = ctp - s_cumT - s_cTb;
        float sumtop = s_svAbove + sv_gt + (float)(64 - (aboveBins + cnt_gt)) * ttop;
        float dis_pos = sumtop / 64.0f;
        float contra = log1pf(Sexp * expf(-dis_pos * invT));
        atomicAdd(&g_contra, (double)contra);
    }
}

__global__ void k_final(float* __restrict__ out_loss) {
    float m = (float)(g_mse / 4194304.0);
    float contra = (float)(g_contra / 1024.0);
    out_loss[0] = 1.25f * m + contra;
}

extern "C" void kernel_launch(void* const* d_in, const int* in_sizes, int n_in,
                              void* d_out, int out_size) {
    const float* z  = (const float*)d_in[0];
    const float* ew = (const float*)d_in[1];
    const float* ep = (const float*)d_in[2];
    float* out = (float*)d_out;
    k_init<<<256, 256>>>();
    k_norm_z<<<B_TOT / 8, 256>>>(z);
    k_norm_c<<<N_EMB / 8, 256>>>(ew);
    k_gemm_tc<<<dim3(N_EMB / 128, B_TOT / 128), 256>>>();
    k_rows<<<B_TOT / 4, 256>>>(z, ew, out, out + OUT_IDX);
    k_cols<<<N_EMB, 64>>>(z, ew, ep, out + OUT_NW, out + OUT_EP);
    k_select<<<N_EMB, 512>>>();
    k_final<<<1, 1>>>(out + OUT_LOSS);
}

// round 12
// speedup vs baseline: 1.1232x; 1.1232x over previous
#include <cuda_runtime.h>
#include <cuda_bf16.h>
#include <cstdint>

#define B_TOT 65536
#define N_EMB 1024
#define KMED  32768
#define TEMP_F 0.07f

#define OUT_LOSS 4194304
#define OUT_IDX  4194305
#define OUT_NW   4259841
#define OUT_EP   4325377

#define WLO  (-0.01f)
#define WHI  (0.01f)
#define TOPT (0.33f)
#define EXLO (-0.28f)
#define WCAP 8192
#define TCAP 1024
#define WBCAP 32
#define TBCAP 8
#define HB   256
#define GCAP 256

#define TSTRIDE 144         // bytes per tile row: 64 bf16 data + 8 pad (odd 16B mult)
#define TBYTES  (128 * TSTRIDE)
#define SMEM_TC (6 * TBYTES)   // 110592

// bf16 triple-split operands (row-major, 64 bf16 = 128B rows)
__device__ __nv_bfloat162 g_a1[(size_t)B_TOT * 32];
__device__ __nv_bfloat162 g_a2[(size_t)B_TOT * 32];
__device__ __nv_bfloat162 g_a3[(size_t)B_TOT * 32];
__device__ __nv_bfloat162 g_b1[N_EMB * 32];
__device__ __nv_bfloat162 g_b2[N_EMB * 32];
__device__ __nv_bfloat162 g_b3[N_EMB * 32];
__device__ unsigned long long g_rowmax[B_TOT];
__device__ unsigned long long g_colmax[N_EMB];
__device__ int g_counts[N_EMB];
__device__ double g_mse;
__device__ double g_contra;
__device__ float    g_W[(size_t)N_EMB * WCAP];
__device__ float    g_T[(size_t)N_EMB * TCAP];
__device__ unsigned g_wc[N_EMB];
__device__ unsigned g_tc[N_EMB];
__device__ int      g_cnt_lo[N_EMB];
__device__ float    g_se_lo[N_EMB];

__device__ __forceinline__ unsigned keyf(float f) {
    unsigned u = __float_as_uint(f);
    return (u & 0x80000000u) ? ~u : (u | 0x80000000u);
}
__device__ __forceinline__ unsigned long long packvi(float v, unsigned idx) {
    return ((unsigned long long)keyf(v) << 32) | (unsigned long long)(0xFFFFFFFFu - idx);
}
__device__ __forceinline__ uint32_t smem_u32(const void* p) {
    uint32_t a;
    asm("{ .reg .u64 t; cvta.to.shared.u64 t, %1; cvt.u32.u64 %0, t; }" : "=r"(a) : "l"(p));
    return a;
}

__global__ void k_init() {
    int i = blockIdx.x * blockDim.x + threadIdx.x;
    if (i < B_TOT) g_rowmax[i] = 0ull;
    if (i < N_EMB) {
        g_colmax[i] = 0ull; g_counts[i] = 0;
        g_wc[i] = 0u; g_tc[i] = 0u; g_cnt_lo[i] = 0; g_se_lo[i] = 0.f;
    }
    if (i == 0) { g_mse = 0.0; g_contra = 0.0; }
}

__device__ __forceinline__ void norm_split(const float* __restrict__ in,
                                           __nv_bfloat162* o1, __nv_bfloat162* o2,
                                           __nv_bfloat162* o3, int row, int lane) {
    float2 v = ((const float2*)(in + (size_t)row * 64))[lane];
    float s = v.x * v.x + v.y * v.y;
    #pragma unroll
    for (int o = 16; o; o >>= 1) s += __shfl_xor_sync(0xFFFFFFFFu, s, o);
    float dn = fmaxf(sqrtf(s), 1e-12f);
    float nx = v.x / dn, ny = v.y / dn;
    __nv_bfloat16 x1 = __float2bfloat16(nx), y1 = __float2bfloat16(ny);
    float rx = nx - __bfloat162float(x1), ry = ny - __bfloat162float(y1);
    __nv_bfloat16 x2 = __float2bfloat16(rx), y2 = __float2bfloat16(ry);
    rx -= __bfloat162float(x2); ry -= __bfloat162float(y2);
    __nv_bfloat16 x3 = __float2bfloat16(rx), y3 = __float2bfloat16(ry);
    size_t idx = (size_t)row * 32 + lane;
    o1[idx] = __nv_bfloat162(x1, y1);
    o2[idx] = __nv_bfloat162(x2, y2);
    o3[idx] = __nv_bfloat162(x3, y3);
}
__global__ void k_norm_z(const float* __restrict__ z) {
    int w = (blockIdx.x * blockDim.x + threadIdx.x) >> 5;
    if (w < B_TOT) norm_split(z, g_a1, g_a2, g_a3, w, threadIdx.x & 31);
}
__global__ void k_norm_c(const float* __restrict__ ew) {
    int w = (blockIdx.x * blockDim.x + threadIdx.x) >> 5;
    if (w < N_EMB) norm_split(ew, g_b1, g_b2, g_b3, w, threadIdx.x & 31);
}

// tensor-core GEMM via mma.sync bf16, 6-term split, full-K smem, fused epilogue.
__global__ __launch_bounds__(256, 2) void k_gemm_tc() {
    extern __shared__ __align__(16) char smem[];
    int tid = threadIdx.x, wid = tid >> 5, lane = tid & 31;
    int warp_m = wid >> 2, warp_n = wid & 3;          // 2 x 4 warp grid
    int n0 = blockIdx.x * 128, m0 = blockIdx.y * 128;
    uint32_t sb = smem_u32(smem);

    float acc[4][4][4];
    #pragma unroll
    for (int a = 0; a < 4; a++)
        #pragma unroll
        for (int b = 0; b < 4; b++)
            #pragma unroll
            for (int c = 0; c < 4; c++) acc[a][b][c] = 0.f;

    const char* srcs[6] = {
        (const char*)(g_a1 + (size_t)m0 * 32), (const char*)(g_a2 + (size_t)m0 * 32),
        (const char*)(g_a3 + (size_t)m0 * 32), (const char*)(g_b1 + (size_t)n0 * 32),
        (const char*)(g_b2 + (size_t)n0 * 32), (const char*)(g_b3 + (size_t)n0 * 32)};

    // load 6 full-K tiles: 128 rows x 128B each, coalesced (32 rows per pass)
    {
        int rr0 = tid >> 3, u = tid & 7;
        #pragma unroll
        for (int t = 0; t < 6; t++) {
            const char* src = srcs[t];
            char* dst = smem + t * TBYTES;
            #pragma unroll
            for (int p = 0; p < 4; p++) {
                int r = rr0 + p * 32;
                *(uint4*)(dst + r * TSTRIDE + u * 16) = *(const uint4*)(src + r * 128 + u * 16);
            }
        }
    }
    __syncthreads();

    const int TA[6] = {0, 0, 1, 0, 2, 1};
    const int TB[6] = {0, 1, 0, 2, 0, 1};
    // ldmatrix per-thread address components
    uint32_t aRow = (uint32_t)(warp_m * 64 + (lane & 7) + ((lane >> 3) & 1) * 8);
    uint32_t aKof = (uint32_t)((lane >> 4) * 16);
    int lb = lane & 15;
    uint32_t bRow = (uint32_t)(warp_n * 32 + (lb & 7));
    uint32_t bKof = (uint32_t)((lb >> 3) * 16);

    for (int kt = 0; kt < 4; kt++) {
        uint32_t kof = (uint32_t)(kt * 32);
        #pragma unroll
        for (int t = 0; t < 6; t++) {
            uint32_t tAb = sb + TA[t] * TBYTES;
            uint32_t tBb = sb + (3 + TB[t]) * TBYTES;
            uint32_t bf[4][2];
            #pragma unroll
            for (int nt = 0; nt < 4; nt++) {
                uint32_t addr = tBb + (bRow + nt * 8) * TSTRIDE + bKof + kof;
                asm volatile("ldmatrix.sync.aligned.m8n8.x2.shared.b16 {%0,%1}, [%2];"
                             : "=r"(bf[nt][0]), "=r"(bf[nt][1]) : "r"(addr));
            }
            #pragma unroll
            for (int mt = 0; mt < 4; mt++) {
                uint32_t a0, a1, a2, a3;
                uint32_t addr = tAb + (aRow + mt * 16) * TSTRIDE + aKof + kof;
                asm volatile("ldmatrix.sync.aligned.m8n8.x4.shared.b16 {%0,%1,%2,%3}, [%4];"
                             : "=r"(a0), "=r"(a1), "=r"(a2), "=r"(a3) : "r"(addr));
                #pragma unroll
                for (int nt = 0; nt < 4; nt++) {
                    asm volatile(
                        "mma.sync.aligned.m16n8k16.row.col.f32.bf16.bf16.f32 "
                        "{%0,%1,%2,%3},{%4,%5,%6,%7},{%8,%9},{%0,%1,%2,%3};"
                        : "+f"(acc[mt][nt][0]), "+f"(acc[mt][nt][1]),
                          "+f"(acc[mt][nt][2]), "+f"(acc[mt][nt][3])
                        : "r"(a0), "r"(a1), "r"(a2), "r"(a3),
                          "r"(bf[nt][0]), "r"(bf[nt][1]));
                }
            }
        }
    }

    // ---------------- epilogue (aliases smem) ----------------
    __syncthreads();
    unsigned long long* srow_s = (unsigned long long*)smem;          // [128]
    unsigned long long* scol_s = (unsigned long long*)(smem + 1024); // [128]
    int*      s_cnt = (int*)(smem + 2048);
    float*    s_se  = (float*)(smem + 2560);
    unsigned* s_wn  = (unsigned*)(smem + 3072);
    unsigned* s_tn  = (unsigned*)(smem + 3584);
    float*    s_wbuf = (float*)(smem + 4096);                        // [128][WBCAP]
    float*    s_tbuf = (float*)(smem + 20480);                       // [128][TBCAP]
    if (tid < 128) {
        srow_s[tid] = 0ull; scol_s[tid] = 0ull;
        s_cnt[tid] = 0; s_se[tid] = 0.f; s_wn[tid] = 0u; s_tn[tid] = 0u;
    }
    __syncthreads();

    int r0 = lane >> 2, c0 = (lane & 3) * 2;
    #pragma unroll
    for (int mt = 0; mt < 4; mt++)
        #pragma unroll
        for (int h = 0; h < 2; h++) {
            int rl = warp_m * 64 + mt * 16 + h * 8 + r0;
            float bv = -2.f; int bc = 0;
            #pragma unroll
            for (int nt = 0; nt < 4; nt++)
                #pragma unroll
                for (int q = 0; q < 2; q++) {
                    float v = acc[mt][nt][h * 2 + q];
                    int c = warp_n * 32 + nt * 8 + c0 + q;
                    if (v > bv) { bv = v; bc = c; }
                }
            unsigned long long m = packvi(bv, (unsigned)(n0 + bc));
            #pragma unroll
            for (int o = 1; o < 4; o <<= 1) {
                unsigned long long v = __shfl_xor_sync(0xFFFFFFFFu, m, o);
                if (v > m) m = v;
            }
            if ((lane & 3) == 0) atomicMax(&srow_s[rl], m);
        }
    #pragma unroll
    for (int nt = 0; nt < 4; nt++)
        #pragma unroll
        for (int q = 0; q < 2; q++) {
            int cl = warp_n * 32 + nt * 8 + c0 + q;
            float bv = -2.f; int br = 0;
            #pragma unroll
            for (int mt = 0; mt < 4; mt++)
                #pragma unroll
                for (int h = 0; h < 2; h++) {
                    float v = acc[mt][nt][h * 2 + q];
                    if (v > bv) { bv = v; br = warp_m * 64 + mt * 16 + h * 8 + r0; }
                }
            unsigned long long m = packvi(bv, (unsigned)(m0 + br));
            #pragma unroll
            for (int o = 4; o < 32; o <<= 1) {
                unsigned long long v = __shfl_xor_sync(0xFFFFFFFFu, m, o);
                if (v > m) m = v;
            }
            if ((lane >> 2) == 0) atomicMax(&scol_s[cl], m);
        }
    const float invT = 1.0f / TEMP_F;
    #pragma unroll
    for (int nt = 0; nt < 4; nt++)
        #pragma unroll
        for (int q = 0; q < 2; q++) {
            int cl = warp_n * 32 + nt * 8 + c0 + q;
            int n = n0 + cl;
            int cnt = 0; float se = 0.f;
            #pragma unroll
            for (int mt = 0; mt < 4; mt++)
                #pragma unroll
                for (int h = 0; h < 2; h++) {
                    float v = acc[mt][nt][h * 2 + q];
                    if (v < WLO) {
                        cnt++;
                        if (v >= EXLO) se += __expf(v * invT);
                    } else if (v < WHI) {
                        unsigned p = atomicAdd(&s_wn[cl], 1u);
                        if (p < WBCAP) s_wbuf[cl * WBCAP + p] = v;
                        else { unsigned g = atomicAdd(&g_wc[n], 1u); if (g < WCAP) g_W[(size_t)n * WCAP + g] = v; }
                    } else if (v >= TOPT) {
                        unsigned p = atomicAdd(&s_tn[cl], 1u);
                        if (p < TBCAP) s_tbuf[cl * TBCAP + p] = v;
                        else { unsigned g = atomicAdd(&g_tc[n], 1u); if (g < TCAP) g_T[(size_t)n * TCAP + g] = v; }
                    }
                }
            if (cnt) { atomicAdd(&s_cnt[cl], cnt); if (se != 0.f) atomicAdd(&s_se[cl], se); }
        }
    __syncthreads();
    if (tid < 128) {
        int n = n0 + tid;
        atomicMax(&g_rowmax[m0 + tid], srow_s[tid]);
        atomicMax(&g_colmax[n], scol_s[tid]);
        if (s_cnt[tid]) atomicAdd(&g_cnt_lo[n], s_cnt[tid]);
        if (s_se[tid] != 0.f) atomicAdd(&g_se_lo[n], s_se[tid]);
        unsigned wn = min(s_wn[tid], (unsigned)WBCAP);
        if (wn) {
            unsigned base = atomicAdd(&g_wc[n], wn);
            for (unsigned h = 0; h < wn; h++)
                if (base + h < WCAP) g_W[(size_t)n * WCAP + base + h] = s_wbuf[tid * WBCAP + h];
        }
        unsigned tn = min(s_tn[tid], (unsigned)TBCAP);
        if (tn) {
            unsigned base = atomicAdd(&g_tc[n], tn);
            for (unsigned h = 0; h < tn; h++)
                if (base + h < TCAP) g_T[(size_t)n * TCAP + base + h] = s_tbuf[tid * TBCAP + h];
        }
    }
}

__global__ __launch_bounds__(256) void k_rows(const float* __restrict__ z,
                                              const float* __restrict__ ew,
                                              float* __restrict__ out_zq,
                                              float* __restrict__ out_idx) {
    int tid = threadIdx.x;
    int b = blockIdx.x * 4 + (tid >> 6);
    int d = tid & 63;
    unsigned nIdx = 0xFFFFFFFFu - (unsigned)(g_rowmax[b] & 0xFFFFFFFFull);
    float w  = ew[(size_t)nIdx * 64 + d];
    float zv = z[(size_t)b * 64 + d];
    float dq = w - zv;
    out_zq[(size_t)b * 64 + d] = zv + dq;
    float sq = dq * dq;
    #pragma unroll
    for (int o = 16; o; o >>= 1) sq += __shfl_xor_sync(0xFFFFFFFFu, sq, o);
    __shared__ float red[8];
    if ((tid & 31) == 0) red[tid >> 5] = sq;
    __syncthreads();
    if (tid == 0) {
        float s = 0.f;
        #pragma unroll
        for (int i = 0; i < 8; i++) s += red[i];
        atomicAdd(&g_mse, (double)s);
    }
    if (d == 0) {
        atomicAdd(&g_counts[nIdx], 1);
        out_idx[b] = (float)nIdx;
    }
}

__global__ __launch_bounds__(64) void k_cols(const float* __restrict__ z,
                                             const float* __restrict__ ew,
                                             const float* __restrict__ eprob,
                                             float* __restrict__ out_nw,
                                             float* __restrict__ out_ep) {
    int n = blockIdx.x, d = threadIdx.x;
    __shared__ float s_dec;
    __shared__ unsigned s_anchor;
    if (d == 0) {
        float cnt = (float)g_counts[n];
        float ep = eprob[n] * 0.99f + (cnt / 65536.0f) * 0.01f;
        out_ep[n] = ep;
        s_dec = expf(-((ep * 1024.0f * 10.0f) / 0.01f) - 0.001f);
        s_anchor = 0xFFFFFFFFu - (unsigned)(g_colmax[n] & 0xFFFFFFFFull);
    }
    __syncthreads();
    float dec = s_dec;
    float w = ew[(size_t)n * 64 + d];
    out_nw[(size_t)n * 64 + d] = w * (1.0f - dec) + z[(size_t)s_anchor * 64 + d] * dec;
}

__global__ __launch_bounds__(512) void k_select() {
    __shared__ unsigned cW[HB]; __shared__ float eW[HB];
    __shared__ unsigned cT[HB]; __shared__ float vT[HB];
    __shared__ float GW[GCAP], GT[GCAP];
    __shared__ unsigned s_gw, s_gt;
    __shared__ int s_bW, s_cumW, s_bT, s_cumT, s_cTb;
    __shared__ float s_seBelow, s_svAbove, s_tmed, s_ttop;
    int tid = threadIdx.x;
    int n = blockIdx.x;
    int cw  = (int)min(g_wc[n], (unsigned)WCAP);
    int ctp = (int)min(g_tc[n], (unsigned)TCAP);
    int C_lo = g_cnt_lo[n];
    float se_lo = g_se_lo[n];
    const float* Wp = &g_W[(size_t)n * WCAP];
    const float* Tp = &g_T[(size_t)n * TCAP];
    for (int i = tid; i < HB; i += 512) { cW[i] = 0u; eW[i] = 0.f; cT[i] = 0u; vT[i] = 0.f; }
    if (tid == 0) { s_gw = 0u; s_gt = 0u; s_tmed = WLO; s_ttop = TOPT; }
    __syncthreads();
    const float invT = 1.0f / TEMP_F;
    const float sclW = (float)HB / (WHI - WLO);
    const float sclT = (float)HB / (1.0f - TOPT);
    for (int i = tid; i < cw; i += 512) {
        float v = Wp[i];
        int b = min(max((int)((v - WLO) * sclW), 0), HB - 1);
        atomicAdd(&cW[b], 1u); atomicAdd(&eW[b], __expf(v * invT));
    }
    for (int i = tid; i < ctp; i += 512) {
        float v = Tp[i];
        int b = min(max((int)((v - TOPT) * sclT), 0), HB - 1);
        atomicAdd(&cT[b], 1u); atomicAdd(&vT[b], v);
    }
    __syncthreads();
    if (tid == 0) {
        int r = KMED - C_lo; if (r < 1) r = 1;
        int cum = 0; float se = 0.f; int b = 0;
        for (;; b++) { if (cum + (int)cW[b] >= r || b == HB - 1) break; cum += (int)cW[b]; se += eW[b]; }
        s_bW = b; s_cumW = cum; s_seBelow = se;
    } else if (tid == 32) {
        int r = ctp - 63; if (r < 1) r = 1;
        int cum = 0; int b = 0;
        for (;; b++) { if (cum + (int)cT[b] >= r || b == HB - 1) break; cum += (int)cT[b]; }
        float tot = 0.f, below = 0.f;
        for (int q = 0; q < HB; q++) tot += vT[q];
        for (int q = 0; q < b; q++) below += vT[q];
        s_bT = b; s_cumT = cum; s_cTb = (int)cT[b]; s_svAbove = tot - below - vT[b];
    }
    __syncthreads();
    int bW = s_bW, bT = s_bT;
    for (int i = tid; i < cw; i += 512) {
        float v = Wp[i];
        int b = min(max((int)((v - WLO) * sclW), 0), HB - 1);
        if (b == bW) { unsigned p = atomicAdd(&s_gw, 1u); if (p < GCAP) GW[p] = v; }
    }
    for (int i = tid; i < ctp; i += 512) {
        float v = Tp[i];
        int b = min(max((int)((v - TOPT) * sclT), 0), HB - 1);
        if (b == bT) { unsigned p = atomicAdd(&s_gt, 1u); if (p < GCAP) GT[p] = v; }
    }
    __syncthreads();
    int mW = (int)min(s_gw, (unsigned)GCAP);
    int mT = (int)min(s_gt, (unsigned)GCAP);
    int rW = KMED - C_lo - s_cumW; if (rW < 1) rW = 1; if (rW > mW) rW = mW;
    int rT = (ctp - 63) - s_cumT;  if (rT < 1) rT = 1; if (rT > mT) rT = mT;
    if (tid < mW) {
        float x = GW[tid]; int less = 0, eqb = 0;
        for (int j = 0; j < mW; j++) { float y = GW[j]; less += (y < x); eqb += (j < tid) && (y == x); }
        if (less + eqb + 1 == rW) s_tmed = x;
    }
    if (tid >= 256 && tid - 256 < mT) {
        int i = tid - 256; float x = GT[i]; int less = 0, eqb = 0;
        for (int j = 0; j < mT; j++) { float y = GT[j]; less += (y < x); eqb += (j < i) && (y == x); }
        if (less + eqb + 1 == rT) s_ttop = x;
    }
    __syncthreads();
    if (tid == 0) {
        float tmed = s_tmed, ttop = s_ttop;
        int cnt_lt = 0; float se_lt = 0.f;
        for (int j = 0; j < mW; j++) if (GW[j] < tmed) { cnt_lt++; se_lt += __expf(GW[j] * invT); }
        float Sexp = se_lo + s_seBelow + se_lt
                   + (float)(KMED - C_lo - s_cumW - cnt_lt) * __expf(tmed * invT);
        int cnt_gt = 0; float sv_gt = 0.f;
        for (int j = 0; j < mT; j++) if (GT[j] > ttop) { cnt_gt++; sv_gt += GT[j]; }
        int aboveBins = ctp - s_cumT - s_cTb;
        float sumtop = s_svAbove + sv_gt + (float)(64 - (aboveBins + cnt_gt)) * ttop;
        float dis_pos = sumtop / 64.0f;
        float contra = log1pf(Sexp * expf(-dis_pos * invT));
        atomicAdd(&g_contra, (double)contra);
    }
}

__global__ void k_final(float* __restrict__ out_loss) {
    float m = (float)(g_mse / 4194304.0);
    float contra = (float)(g_contra / 1024.0);
    out_loss[0] = 1.25f * m + contra;
}

extern "C" void kernel_launch(void* const* d_in, const int* in_sizes, int n_in,
                              void* d_out, int out_size) {
    const float* z  = (const float*)d_in[0];
    const float* ew = (const float*)d_in[1];
    const float* ep = (const float*)d_in[2];
    float* out = (float*)d_out;
    cudaFuncSetAttribute(k_gemm_tc, cudaFuncAttributeMaxDynamicSharedMemorySize, SMEM_TC);
    k_init<<<256, 256>>>();
    k_norm_z<<<B_TOT / 8, 256>>>(z);
    k_norm_c<<<N_EMB / 8, 256>>>(ew);
    k_gemm_tc<<<dim3(N_EMB / 128, B_TOT / 128), 256, SMEM_TC>>>();
    k_rows<<<B_TOT / 4, 256>>>(z, ew, out, out + OUT_IDX);
    k_cols<<<N_EMB, 64>>>(z, ew, ep, out + OUT_NW, out + OUT_EP);
    k_select<<<N_EMB, 512>>>();
    k_final<<<1, 1>>>(out + OUT_LOSS);
}